// round 1
// baseline (speedup 1.0000x reference)
#include <cuda_runtime.h>
#include <cuda_bf16.h>

// Problem constants
#define S_LEN 2048
#define B_SZ  2
#define D_MOD 1024
#define H_NUM 16
#define DH_SZ 64
#define WIN_SZ 256
#define M_ROWS (S_LEN * B_SZ)   // 4096

// Scratch (device globals — no allocation allowed)
__device__ float g_swa_Q[M_ROWS * D_MOD];
__device__ float g_swa_K[M_ROWS * D_MOD];
__device__ float g_swa_V[M_ROWS * D_MOD];
__device__ float g_swa_O[M_ROWS * D_MOD];

// ---------------------------------------------------------------------------
// SGEMM: C[M,N] = A[M,K] @ W[K,N] + bias[N]   (all row-major fp32)
// 128x128x8 tiles, 256 threads, 8x8 register microtile per thread.
// M=4096, N=1024, K=1024 -> grid(8,32) = 256 blocks = one full wave @ occ 2.
// ---------------------------------------------------------------------------
#define BM 128
#define BN 128
#define BK 8
#define TM 8
#define TN 8

__global__ __launch_bounds__(256, 2)
void swa_sgemm_bias(const float* __restrict__ A, const float* __restrict__ W,
                    const float* __restrict__ bias, float* __restrict__ C,
                    int M, int N, int K) {
    __shared__ float As[BK][BM];
    __shared__ float Bs[BK][BN];

    const int tid = threadIdx.x;
    const int tx = tid & 15;        // 0..15  -> col group
    const int ty = tid >> 4;        // 0..15  -> row group
    const int m0 = blockIdx.y * BM;
    const int n0 = blockIdx.x * BN;

    float acc[TM][TN];
#pragma unroll
    for (int i = 0; i < TM; ++i)
#pragma unroll
        for (int j = 0; j < TN; ++j) acc[i][j] = 0.0f;

    const int arow = tid >> 1;            // 0..127
    const int acol = (tid & 1) * 4;       // 0 or 4
    const int brow = tid >> 5;            // 0..7
    const int bcol = (tid & 31) * 4;      // 0..124

    const float* Aptr = A + (size_t)(m0 + arow) * K + acol;
    const float* Bptr = W + (size_t)brow * N + n0 + bcol;

    for (int k0 = 0; k0 < K; k0 += BK) {
        float4 av = *(const float4*)(Aptr + k0);
        As[acol + 0][arow] = av.x;
        As[acol + 1][arow] = av.y;
        As[acol + 2][arow] = av.z;
        As[acol + 3][arow] = av.w;
        *(float4*)&Bs[brow][bcol] = *(const float4*)(Bptr + (size_t)k0 * N);
        __syncthreads();

#pragma unroll
        for (int kk = 0; kk < BK; ++kk) {
            float a[TM], b[TN];
            *(float4*)&a[0] = *(const float4*)&As[kk][ty * TM];
            *(float4*)&a[4] = *(const float4*)&As[kk][ty * TM + 4];
            *(float4*)&b[0] = *(const float4*)&Bs[kk][tx * TN];
            *(float4*)&b[4] = *(const float4*)&Bs[kk][tx * TN + 4];
#pragma unroll
            for (int i = 0; i < TM; ++i)
#pragma unroll
                for (int j = 0; j < TN; ++j) acc[i][j] = fmaf(a[i], b[j], acc[i][j]);
        }
        __syncthreads();
    }

#pragma unroll
    for (int i = 0; i < TM; ++i) {
        const int row = m0 + ty * TM + i;
#pragma unroll
        for (int j = 0; j < TN; j += 4) {
            const int col = n0 + tx * TN + j;
            float4 o;
            o.x = acc[i][j + 0] + bias[col + 0];
            o.y = acc[i][j + 1] + bias[col + 1];
            o.z = acc[i][j + 2] + bias[col + 2];
            o.w = acc[i][j + 3] + bias[col + 3];
            *(float4*)&C[(size_t)row * N + col] = o;
        }
    }
}

// ---------------------------------------------------------------------------
// Windowed causal attention with sink column, online softmax.
// grid = (32 q-tiles, 32 heads=z), block = 128 threads.
// Each block: 64 queries; thread pair (tid, tid^1) shares one query, splits
// DH=64 into two 32-lane halves. Sink handled by init m=0, l=1.
// ---------------------------------------------------------------------------
__global__ __launch_bounds__(128)
void swa_attn(const float* __restrict__ Q, const float* __restrict__ K,
              const float* __restrict__ V, const float* __restrict__ beta,
              float* __restrict__ O) {
    __shared__ float Ksh[64][64];
    __shared__ float Vsh[64][64];

    const int z = blockIdx.y;
    const int b = z / H_NUM;
    const int h = z % H_NUM;
    const int q0 = blockIdx.x * 64;
    const int tid = threadIdx.x;
    const int q = q0 + (tid >> 1);
    const int half = tid & 1;

    const float scale = 1.0f / (8.0f * __expf(beta[h]));

    // Load this thread's half of q, pre-scaled
    const float* qptr = Q + ((size_t)(q * B_SZ + b)) * D_MOD + h * DH_SZ + half * 32;
    float qr[32];
#pragma unroll
    for (int i = 0; i < 32; i += 4) {
        float4 v4 = *(const float4*)(qptr + i);
        qr[i + 0] = v4.x * scale;
        qr[i + 1] = v4.y * scale;
        qr[i + 2] = v4.z * scale;
        qr[i + 3] = v4.w * scale;
    }

    float m = 0.0f;   // sink logit = 0 participates in the max
    float l = 1.0f;   // exp(0 - 0) from the sink
    float acc[32];
#pragma unroll
    for (int i = 0; i < 32; ++i) acc[i] = 0.0f;

    int kbeg = q0 - (WIN_SZ - 1);
    if (kbeg < 0) kbeg = 0;
    kbeg &= ~63;   // align to tile

    for (int t = kbeg; t < q0 + 64; t += 64) {
        // Stage K/V tile (64 keys x 64 dims) via float4
#pragma unroll
        for (int it = 0; it < 8; ++it) {
            int f = tid + it * 128;        // float4 index 0..1023
            int kk = f >> 4;
            int d = (f & 15) * 4;
            size_t goff = ((size_t)((t + kk) * B_SZ + b)) * D_MOD + h * DH_SZ + d;
            *(float4*)&Ksh[kk][d] = *(const float4*)(K + goff);
            *(float4*)&Vsh[kk][d] = *(const float4*)(V + goff);
        }
        __syncthreads();

#pragma unroll
        for (int c = 0; c < 4; ++c) {
            float sc[16];
#pragma unroll
            for (int kk = 0; kk < 16; ++kk) {
                const float* kp = &Ksh[c * 16 + kk][half * 32];
                float p = 0.0f;
#pragma unroll
                for (int i = 0; i < 32; ++i) p = fmaf(qr[i], kp[i], p);
                p += __shfl_xor_sync(0xffffffffu, p, 1);
                const int kidx = t + c * 16 + kk;
                const bool valid = (kidx <= q) && ((q - kidx) < WIN_SZ);
                sc[kk] = valid ? p : -1e30f;
            }
            float mn = m;
#pragma unroll
            for (int kk = 0; kk < 16; ++kk) mn = fmaxf(mn, sc[kk]);
            const float fs = __expf(m - mn);
            l *= fs;
#pragma unroll
            for (int i = 0; i < 32; ++i) acc[i] *= fs;
#pragma unroll
            for (int kk = 0; kk < 16; ++kk) {
                const float p = __expf(sc[kk] - mn);
                l += p;
                const float* vp = &Vsh[c * 16 + kk][half * 32];
#pragma unroll
                for (int i = 0; i < 32; ++i) acc[i] = fmaf(p, vp[i], acc[i]);
            }
            m = mn;
        }
        __syncthreads();
    }

    const float rl = 1.0f / l;
    float* optr = O + ((size_t)(q * B_SZ + b)) * D_MOD + h * DH_SZ + half * 32;
#pragma unroll
    for (int i = 0; i < 32; i += 4) {
        float4 v4;
        v4.x = acc[i + 0] * rl;
        v4.y = acc[i + 1] * rl;
        v4.z = acc[i + 2] * rl;
        v4.w = acc[i + 3] * rl;
        *(float4*)(optr + i) = v4;
    }
}

// ---------------------------------------------------------------------------
extern "C" void kernel_launch(void* const* d_in, const int* in_sizes, int n_in,
                              void* d_out, int out_size) {
    const float* x    = (const float*)d_in[0];
    const float* beta = (const float*)d_in[1];
    const float* Wq   = (const float*)d_in[2];
    const float* bq   = (const float*)d_in[3];
    const float* Wk   = (const float*)d_in[4];
    const float* bk   = (const float*)d_in[5];
    const float* Wv   = (const float*)d_in[6];
    const float* bv   = (const float*)d_in[7];
    const float* Wo   = (const float*)d_in[8];
    const float* bo   = (const float*)d_in[9];
    float* out = (float*)d_out;

    float *Qp, *Kp, *Vp, *Op;
    cudaGetSymbolAddress((void**)&Qp, g_swa_Q);
    cudaGetSymbolAddress((void**)&Kp, g_swa_K);
    cudaGetSymbolAddress((void**)&Vp, g_swa_V);
    cudaGetSymbolAddress((void**)&Op, g_swa_O);

    dim3 ggrid(D_MOD / BN, M_ROWS / BM);   // (8, 32)
    swa_sgemm_bias<<<ggrid, 256>>>(x, Wq, bq, Qp, M_ROWS, D_MOD, D_MOD);
    swa_sgemm_bias<<<ggrid, 256>>>(x, Wk, bk, Kp, M_ROWS, D_MOD, D_MOD);
    swa_sgemm_bias<<<ggrid, 256>>>(x, Wv, bv, Vp, M_ROWS, D_MOD, D_MOD);

    dim3 agrid(S_LEN / 64, B_SZ * H_NUM);  // (32, 32)
    swa_attn<<<agrid, 128>>>(Qp, Kp, Vp, beta, Op);

    swa_sgemm_bias<<<ggrid, 256>>>(Op, Wo, bo, out, M_ROWS, D_MOD, D_MOD);
}

// round 2
// speedup vs baseline: 2.6681x; 2.6681x over previous
#include <cuda_runtime.h>
#include <cuda_bf16.h>
#include <cstdint>

#define S_LEN 2048
#define B_SZ  2
#define D_MOD 1024
#define H_NUM 16
#define DH_SZ 64
#define WIN_SZ 256
#define M_ROWS (S_LEN * B_SZ)   // 4096

// Scratch (device globals — no allocation allowed)
__device__ float g_swa_Q[M_ROWS * D_MOD];
__device__ float g_swa_K[M_ROWS * D_MOD];
__device__ float g_swa_V[M_ROWS * D_MOD];
__device__ float g_swa_O[M_ROWS * D_MOD];

// ---------------------------------------------------------------------------
// helpers
// ---------------------------------------------------------------------------
__device__ __forceinline__ uint32_t f2tf32(float x) {
    uint32_t r;
    asm("cvt.rna.tf32.f32 %0, %1;" : "=r"(r) : "f"(x));
    return r;
}

__device__ __forceinline__ void cp16(uint32_t dst_smem, const void* src) {
    asm volatile("cp.async.cg.shared.global [%0], [%1], 16;"
                 :: "r"(dst_smem), "l"(src));
}

__device__ __forceinline__ void mma_tf32(float c[4], const uint32_t a[4],
                                         const uint32_t b[2]) {
    asm volatile(
        "mma.sync.aligned.m16n8k8.row.col.f32.tf32.tf32.f32 "
        "{%0,%1,%2,%3}, {%4,%5,%6,%7}, {%8,%9}, {%0,%1,%2,%3};"
        : "+f"(c[0]), "+f"(c[1]), "+f"(c[2]), "+f"(c[3])
        : "r"(a[0]), "r"(a[1]), "r"(a[2]), "r"(a[3]), "r"(b[0]), "r"(b[1]));
}

// ---------------------------------------------------------------------------
// tf32 tensor-core GEMM: C[4096,1024] = A[4096,1024] @ W[1024,1024] + bias
// 128x128x16 tiles, 256 threads (8 warps, 64x32 warp tiles), cp.async
// double buffering. K = N = 1024 fixed.
// ---------------------------------------------------------------------------
__global__ __launch_bounds__(256, 2)
void swa_gemm_tf32(const float* __restrict__ A, const float* __restrict__ W,
                   const float* __restrict__ bias, float* __restrict__ C) {
    __shared__ float As[2][128][20];   // [m][k], pad 4 -> conflict-free frags
    __shared__ float Bs[2][16][136];   // [k][n], pad 8 -> conflict-free frags

    const int tid  = threadIdx.x;
    const int lane = tid & 31;
    const int warp = tid >> 5;
    const int wr   = warp & 1;          // 0..1  -> m offset 64*wr
    const int wc   = warp >> 1;         // 0..3  -> n offset 32*wc
    const int m0   = blockIdx.y * 128;
    const int n0   = blockIdx.x * 128;

    // cp.async mapping
    const int arow = tid >> 1;          // 0..127
    const int ac0  = (tid & 1) * 8;     // 0 or 8 (floats)
    const int brow = tid >> 4;          // 0..15
    const int bc0  = (tid & 15) * 8;    // 0..120

    const float* Ag = A + (size_t)(m0 + arow) * 1024 + ac0;
    const float* Bg = W + (size_t)brow * 1024 + n0 + bc0;

    float acc[4][4][4];
#pragma unroll
    for (int mt = 0; mt < 4; ++mt)
#pragma unroll
        for (int nt = 0; nt < 4; ++nt)
#pragma unroll
            for (int i = 0; i < 4; ++i) acc[mt][nt][i] = 0.0f;

    // prologue: stage 0
    {
        uint32_t da = (uint32_t)__cvta_generic_to_shared(&As[0][arow][ac0]);
        cp16(da, Ag);
        cp16(da + 16, Ag + 4);
        uint32_t db = (uint32_t)__cvta_generic_to_shared(&Bs[0][brow][bc0]);
        cp16(db, Bg);
        cp16(db + 16, Bg + 4);
        asm volatile("cp.async.commit_group;");
    }

    const int NIT = 1024 / 16;  // 64
    for (int it = 0; it < NIT; ++it) {
        if (it + 1 < NIT) {
            const int s = (it + 1) & 1;
            const int k0 = (it + 1) * 16;
            uint32_t da = (uint32_t)__cvta_generic_to_shared(&As[s][arow][ac0]);
            cp16(da, Ag + k0);
            cp16(da + 16, Ag + k0 + 4);
            uint32_t db = (uint32_t)__cvta_generic_to_shared(&Bs[s][brow][bc0]);
            cp16(db, Bg + (size_t)k0 * 1024);
            cp16(db + 16, Bg + (size_t)k0 * 1024 + 4);
            asm volatile("cp.async.commit_group;");
            asm volatile("cp.async.wait_group 1;");
        } else {
            asm volatile("cp.async.wait_group 0;");
        }
        __syncthreads();

        const int s = it & 1;
        const int r  = lane >> 2;   // 0..7
        const int kq = lane & 3;    // 0..3
#pragma unroll
        for (int ks = 0; ks < 2; ++ks) {
            const int k8 = ks * 8;
            uint32_t af[4][4], bf[4][2];
#pragma unroll
            for (int mt = 0; mt < 4; ++mt) {
                const int m = wr * 64 + mt * 16 + r;
                af[mt][0] = f2tf32(As[s][m][k8 + kq]);
                af[mt][1] = f2tf32(As[s][m + 8][k8 + kq]);
                af[mt][2] = f2tf32(As[s][m][k8 + kq + 4]);
                af[mt][3] = f2tf32(As[s][m + 8][k8 + kq + 4]);
            }
#pragma unroll
            for (int nt = 0; nt < 4; ++nt) {
                const int n = wc * 32 + nt * 8 + r;
                bf[nt][0] = f2tf32(Bs[s][k8 + kq][n]);
                bf[nt][1] = f2tf32(Bs[s][k8 + kq + 4][n]);
            }
#pragma unroll
            for (int mt = 0; mt < 4; ++mt)
#pragma unroll
                for (int nt = 0; nt < 4; ++nt)
                    mma_tf32(acc[mt][nt], af[mt], bf[nt]);
        }
        __syncthreads();
    }

    // epilogue
#pragma unroll
    for (int mt = 0; mt < 4; ++mt) {
        const int row = m0 + wr * 64 + mt * 16 + (lane >> 2);
#pragma unroll
        for (int nt = 0; nt < 4; ++nt) {
            const int col = n0 + wc * 32 + nt * 8 + 2 * (lane & 3);
            const float2 bia = *(const float2*)&bias[col];
            float2 o0, o1;
            o0.x = acc[mt][nt][0] + bia.x;
            o0.y = acc[mt][nt][1] + bia.y;
            o1.x = acc[mt][nt][2] + bia.x;
            o1.y = acc[mt][nt][3] + bia.y;
            *(float2*)&C[(size_t)row * 1024 + col] = o0;
            *(float2*)&C[(size_t)(row + 8) * 1024 + col] = o1;
        }
    }
}

// ---------------------------------------------------------------------------
// Attention v2: two-phase blocked structure, 64 queries / block, 128 threads.
// Dynamic smem (68096 B): Qsh[64][68] | Ksh[64][64] swz | Vsh[64][64] swz |
//                         Ssh[64][68] ([k][q]) | Fsh[64] | Lsh[64]
// ---------------------------------------------------------------------------
#define OFF_Q 0
#define OFF_K 4352
#define OFF_V 8448
#define OFF_S 12544
#define OFF_F 16896
#define OFF_L 16960
#define ATTN_SMEM_BYTES (17024 * 4)

__global__ __launch_bounds__(128)
void swa_attn2(const float* __restrict__ Q, const float* __restrict__ K,
               const float* __restrict__ V, const float* __restrict__ beta,
               float* __restrict__ O) {
    extern __shared__ float sm[];
    float* Qsh = sm + OFF_Q;            // [64][68]
    float4* K4 = (float4*)(sm + OFF_K); // 64*16 swizzled float4
    float4* V4 = (float4*)(sm + OFF_V);
    float* Ssh = sm + OFF_S;            // [64][68], [k][q]
    float* Fsh = sm + OFF_F;
    float* Lsh = sm + OFF_L;

    const int z  = blockIdx.y;
    const int b  = z / H_NUM;
    const int h  = z % H_NUM;
    const int q0 = blockIdx.x * 64;
    const int tid = threadIdx.x;
    const int qg = tid >> 4;   // 0..7 -> 8 queries each
    const int kg = tid & 15;   // 0..15 -> 4 keys (QK) / 4 dims (PV)

    const float scale = 1.0f / (8.0f * __expf(beta[h]));

    // load Q tile (scaled)
#pragma unroll
    for (int it = 0; it < 8; ++it) {
        const int f = tid + it * 128;
        const int row = f >> 4, c4 = f & 15;
        float4 v = *(const float4*)&Q[((size_t)((q0 + row) * B_SZ + b)) * D_MOD + h * DH_SZ + c4 * 4];
        v.x *= scale; v.y *= scale; v.z *= scale; v.w *= scale;
        *(float4*)&Qsh[row * 68 + c4 * 4] = v;
    }

    float acc[8][4];
#pragma unroll
    for (int i = 0; i < 8; ++i)
#pragma unroll
        for (int j = 0; j < 4; ++j) acc[i][j] = 0.0f;

    float m = 0.0f;   // sink logit participates in max
    float l = 1.0f;   // sink contributes exp(0)

    int kbeg = q0 - (WIN_SZ - 1);
    if (kbeg < 0) kbeg = 0;
    kbeg &= ~63;

    for (int t = kbeg; t < q0 + 64; t += 64) {
        // stage K/V (swizzled float4)
#pragma unroll
        for (int it = 0; it < 8; ++it) {
            const int f = tid + it * 128;
            const int kk = f >> 4, d4 = f & 15;
            const size_t g = ((size_t)((t + kk) * B_SZ + b)) * D_MOD + h * DH_SZ + d4 * 4;
            const int swz = kk * 16 + (d4 ^ (kk & 15));
            K4[swz] = *(const float4*)&K[g];
            V4[swz] = *(const float4*)&V[g];
        }
        __syncthreads();

        // QK: thread tile 8q x 4k (keys strided by 16)
        float s[8][4];
#pragma unroll
        for (int i = 0; i < 8; ++i)
#pragma unroll
            for (int j = 0; j < 4; ++j) s[i][j] = 0.0f;

#pragma unroll
        for (int d4 = 0; d4 < 16; ++d4) {
            float4 bf[4];
            const int sx = d4 ^ kg;  // (kg+16j)&15 == kg
#pragma unroll
            for (int j = 0; j < 4; ++j) bf[j] = K4[(kg + 16 * j) * 16 + sx];
#pragma unroll
            for (int i = 0; i < 8; ++i) {
                const float4 a = *(const float4*)&Qsh[(qg * 8 + i) * 68 + d4 * 4];
#pragma unroll
                for (int j = 0; j < 4; ++j) {
                    s[i][j] = fmaf(a.x, bf[j].x, s[i][j]);
                    s[i][j] = fmaf(a.y, bf[j].y, s[i][j]);
                    s[i][j] = fmaf(a.z, bf[j].z, s[i][j]);
                    s[i][j] = fmaf(a.w, bf[j].w, s[i][j]);
                }
            }
        }
        // mask + store transposed scores
#pragma unroll
        for (int j = 0; j < 4; ++j) {
            const int kl = kg + 16 * j;
            const int kidx = t + kl;
#pragma unroll
            for (int i = 0; i < 8; ++i) {
                const int q = q0 + qg * 8 + i;
                const bool valid = (kidx <= q) && ((q - kidx) < WIN_SZ);
                Ssh[kl * 68 + qg * 8 + i] = valid ? s[i][j] : -1e30f;
            }
        }
        __syncthreads();

        // online softmax: one thread per query (tid < 64)
        if (tid < 64) {
            float mn = m;
#pragma unroll 8
            for (int k = 0; k < 64; ++k) mn = fmaxf(mn, Ssh[k * 68 + tid]);
            const float fs = __expf(m - mn);
            float ls = l * fs;
#pragma unroll 8
            for (int k = 0; k < 64; ++k) {
                const float p = __expf(Ssh[k * 68 + tid] - mn);
                Ssh[k * 68 + tid] = p;
                ls += p;
            }
            m = mn; l = ls;
            Fsh[tid] = fs;
            Lsh[tid] = ls;
        }
        __syncthreads();

        // PV: thread tile 8q x 4d (dims = kg*4..)
        float fr[8];
#pragma unroll
        for (int i = 0; i < 8; ++i) fr[i] = Fsh[qg * 8 + i];
#pragma unroll
        for (int i = 0; i < 8; ++i)
#pragma unroll
            for (int j = 0; j < 4; ++j) acc[i][j] *= fr[i];

#pragma unroll 8
        for (int k = 0; k < 64; ++k) {
            const float4 v4 = V4[k * 16 + (kg ^ (k & 15))];
            const float4 pa = *(const float4*)&Ssh[k * 68 + qg * 8];
            const float4 pb = *(const float4*)&Ssh[k * 68 + qg * 8 + 4];
            acc[0][0] = fmaf(pa.x, v4.x, acc[0][0]); acc[0][1] = fmaf(pa.x, v4.y, acc[0][1]);
            acc[0][2] = fmaf(pa.x, v4.z, acc[0][2]); acc[0][3] = fmaf(pa.x, v4.w, acc[0][3]);
            acc[1][0] = fmaf(pa.y, v4.x, acc[1][0]); acc[1][1] = fmaf(pa.y, v4.y, acc[1][1]);
            acc[1][2] = fmaf(pa.y, v4.z, acc[1][2]); acc[1][3] = fmaf(pa.y, v4.w, acc[1][3]);
            acc[2][0] = fmaf(pa.z, v4.x, acc[2][0]); acc[2][1] = fmaf(pa.z, v4.y, acc[2][1]);
            acc[2][2] = fmaf(pa.z, v4.z, acc[2][2]); acc[2][3] = fmaf(pa.z, v4.w, acc[2][3]);
            acc[3][0] = fmaf(pa.w, v4.x, acc[3][0]); acc[3][1] = fmaf(pa.w, v4.y, acc[3][1]);
            acc[3][2] = fmaf(pa.w, v4.z, acc[3][2]); acc[3][3] = fmaf(pa.w, v4.w, acc[3][3]);
            acc[4][0] = fmaf(pb.x, v4.x, acc[4][0]); acc[4][1] = fmaf(pb.x, v4.y, acc[4][1]);
            acc[4][2] = fmaf(pb.x, v4.z, acc[4][2]); acc[4][3] = fmaf(pb.x, v4.w, acc[4][3]);
            acc[5][0] = fmaf(pb.y, v4.x, acc[5][0]); acc[5][1] = fmaf(pb.y, v4.y, acc[5][1]);
            acc[5][2] = fmaf(pb.y, v4.z, acc[5][2]); acc[5][3] = fmaf(pb.y, v4.w, acc[5][3]);
            acc[6][0] = fmaf(pb.z, v4.x, acc[6][0]); acc[6][1] = fmaf(pb.z, v4.y, acc[6][1]);
            acc[6][2] = fmaf(pb.z, v4.z, acc[6][2]); acc[6][3] = fmaf(pb.z, v4.w, acc[6][3]);
            acc[7][0] = fmaf(pb.w, v4.x, acc[7][0]); acc[7][1] = fmaf(pb.w, v4.y, acc[7][1]);
            acc[7][2] = fmaf(pb.w, v4.z, acc[7][2]); acc[7][3] = fmaf(pb.w, v4.w, acc[7][3]);
        }
        __syncthreads();   // protect K/V/S reuse next tile
    }

    // normalize + store
#pragma unroll
    for (int i = 0; i < 8; ++i) {
        const int q = q0 + qg * 8 + i;
        const float rl = 1.0f / Lsh[qg * 8 + i];
        float4 o;
        o.x = acc[i][0] * rl; o.y = acc[i][1] * rl;
        o.z = acc[i][2] * rl; o.w = acc[i][3] * rl;
        *(float4*)&O[((size_t)(q * B_SZ + b)) * D_MOD + h * DH_SZ + kg * 4] = o;
    }
}

// ---------------------------------------------------------------------------
extern "C" void kernel_launch(void* const* d_in, const int* in_sizes, int n_in,
                              void* d_out, int out_size) {
    const float* x    = (const float*)d_in[0];
    const float* beta = (const float*)d_in[1];
    const float* Wq   = (const float*)d_in[2];
    const float* bq   = (const float*)d_in[3];
    const float* Wk   = (const float*)d_in[4];
    const float* bk   = (const float*)d_in[5];
    const float* Wv   = (const float*)d_in[6];
    const float* bv   = (const float*)d_in[7];
    const float* Wo   = (const float*)d_in[8];
    const float* bo   = (const float*)d_in[9];
    float* out = (float*)d_out;

    float *Qp, *Kp, *Vp, *Op;
    cudaGetSymbolAddress((void**)&Qp, g_swa_Q);
    cudaGetSymbolAddress((void**)&Kp, g_swa_K);
    cudaGetSymbolAddress((void**)&Vp, g_swa_V);
    cudaGetSymbolAddress((void**)&Op, g_swa_O);

    cudaFuncSetAttribute(swa_attn2, cudaFuncAttributeMaxDynamicSharedMemorySize,
                         ATTN_SMEM_BYTES);

    dim3 ggrid(D_MOD / 128, M_ROWS / 128);   // (8, 32)
    swa_gemm_tf32<<<ggrid, 256>>>(x, Wq, bq, Qp);
    swa_gemm_tf32<<<ggrid, 256>>>(x, Wk, bk, Kp);
    swa_gemm_tf32<<<ggrid, 256>>>(x, Wv, bv, Vp);

    dim3 agrid(S_LEN / 64, B_SZ * H_NUM);    // (32, 32)
    swa_attn2<<<agrid, 128, ATTN_SMEM_BYTES>>>(Qp, Kp, Vp, beta, Op);

    swa_gemm_tf32<<<ggrid, 256>>>(Op, Wo, bo, out);
}

// round 3
// speedup vs baseline: 3.4421x; 1.2901x over previous
#include <cuda_runtime.h>
#include <cuda_bf16.h>
#include <cstdint>

#define S_LEN 2048
#define B_SZ  2
#define D_MOD 1024
#define H_NUM 16
#define DH_SZ 64
#define WIN_SZ 256
#define M_ROWS (S_LEN * B_SZ)   // 4096

__device__ float g_swa_Q[M_ROWS * D_MOD];
__device__ float g_swa_K[M_ROWS * D_MOD];
__device__ float g_swa_V[M_ROWS * D_MOD];
__device__ float g_swa_O[M_ROWS * D_MOD];

// ---------------------------------------------------------------------------
__device__ __forceinline__ uint32_t f2tf32(float x) {
    uint32_t r;
    asm("cvt.rna.tf32.f32 %0, %1;" : "=r"(r) : "f"(x));
    return r;
}
__device__ __forceinline__ float tf32f(float x) {
    return __uint_as_float(f2tf32(x));
}

__device__ __forceinline__ void cp16(uint32_t dst_smem, const void* src) {
    asm volatile("cp.async.cg.shared.global [%0], [%1], 16;"
                 :: "r"(dst_smem), "l"(src));
}

__device__ __forceinline__ void mma_tf32(float c[4], const uint32_t a[4],
                                         const uint32_t b0, const uint32_t b1) {
    asm volatile(
        "mma.sync.aligned.m16n8k8.row.col.f32.tf32.tf32.f32 "
        "{%0,%1,%2,%3}, {%4,%5,%6,%7}, {%8,%9}, {%0,%1,%2,%3};"
        : "+f"(c[0]), "+f"(c[1]), "+f"(c[2]), "+f"(c[3])
        : "r"(a[0]), "r"(a[1]), "r"(a[2]), "r"(a[3]), "r"(b0), "r"(b1));
}

// ---------------------------------------------------------------------------
// tf32 GEMM body: C[4096,1024] = A @ W + bias. 128x128x16, 256 thr, dbuf.
// ---------------------------------------------------------------------------
__device__ __forceinline__
void gemm_body(const float* __restrict__ A, const float* __restrict__ W,
               const float* __restrict__ bias, float* __restrict__ C) {
    __shared__ float As[2][128][20];
    __shared__ float Bs[2][16][136];

    const int tid  = threadIdx.x;
    const int lane = tid & 31;
    const int warp = tid >> 5;
    const int wr   = warp & 1;
    const int wc   = warp >> 1;
    const int m0   = blockIdx.y * 128;
    const int n0   = blockIdx.x * 128;

    const int arow = tid >> 1;
    const int ac0  = (tid & 1) * 8;
    const int brow = tid >> 4;
    const int bc0  = (tid & 15) * 8;

    const float* Ag = A + (size_t)(m0 + arow) * 1024 + ac0;
    const float* Bg = W + (size_t)brow * 1024 + n0 + bc0;

    float acc[4][4][4];
#pragma unroll
    for (int mt = 0; mt < 4; ++mt)
#pragma unroll
        for (int nt = 0; nt < 4; ++nt)
#pragma unroll
            for (int i = 0; i < 4; ++i) acc[mt][nt][i] = 0.0f;

    {
        uint32_t da = (uint32_t)__cvta_generic_to_shared(&As[0][arow][ac0]);
        cp16(da, Ag);
        cp16(da + 16, Ag + 4);
        uint32_t db = (uint32_t)__cvta_generic_to_shared(&Bs[0][brow][bc0]);
        cp16(db, Bg);
        cp16(db + 16, Bg + 4);
        asm volatile("cp.async.commit_group;");
    }

    const int NIT = 1024 / 16;
    for (int it = 0; it < NIT; ++it) {
        if (it + 1 < NIT) {
            const int s = (it + 1) & 1;
            const int k0 = (it + 1) * 16;
            uint32_t da = (uint32_t)__cvta_generic_to_shared(&As[s][arow][ac0]);
            cp16(da, Ag + k0);
            cp16(da + 16, Ag + k0 + 4);
            uint32_t db = (uint32_t)__cvta_generic_to_shared(&Bs[s][brow][bc0]);
            cp16(db, Bg + (size_t)k0 * 1024);
            cp16(db + 16, Bg + (size_t)k0 * 1024 + 4);
            asm volatile("cp.async.commit_group;");
            asm volatile("cp.async.wait_group 1;");
        } else {
            asm volatile("cp.async.wait_group 0;");
        }
        __syncthreads();

        const int s = it & 1;
        const int r  = lane >> 2;
        const int kq = lane & 3;
#pragma unroll
        for (int ks = 0; ks < 2; ++ks) {
            const int k8 = ks * 8;
            uint32_t af[4][4], bf[4][2];
#pragma unroll
            for (int mt = 0; mt < 4; ++mt) {
                const int m = wr * 64 + mt * 16 + r;
                af[mt][0] = f2tf32(As[s][m][k8 + kq]);
                af[mt][1] = f2tf32(As[s][m + 8][k8 + kq]);
                af[mt][2] = f2tf32(As[s][m][k8 + kq + 4]);
                af[mt][3] = f2tf32(As[s][m + 8][k8 + kq + 4]);
            }
#pragma unroll
            for (int nt = 0; nt < 4; ++nt) {
                const int n = wc * 32 + nt * 8 + r;
                bf[nt][0] = f2tf32(Bs[s][k8 + kq][n]);
                bf[nt][1] = f2tf32(Bs[s][k8 + kq + 4][n]);
            }
#pragma unroll
            for (int mt = 0; mt < 4; ++mt)
#pragma unroll
                for (int nt = 0; nt < 4; ++nt)
                    mma_tf32(acc[mt][nt], af[mt], bf[nt][0], bf[nt][1]);
        }
        __syncthreads();
    }

#pragma unroll
    for (int mt = 0; mt < 4; ++mt) {
        const int row = m0 + wr * 64 + mt * 16 + (lane >> 2);
#pragma unroll
        for (int nt = 0; nt < 4; ++nt) {
            const int col = n0 + wc * 32 + nt * 8 + 2 * (lane & 3);
            const float2 bia = *(const float2*)&bias[col];
            float2 o0, o1;
            o0.x = acc[mt][nt][0] + bia.x;
            o0.y = acc[mt][nt][1] + bia.y;
            o1.x = acc[mt][nt][2] + bia.x;
            o1.y = acc[mt][nt][3] + bia.y;
            *(float2*)&C[(size_t)row * 1024 + col] = o0;
            *(float2*)&C[(size_t)(row + 8) * 1024 + col] = o1;
        }
    }
}

__global__ __launch_bounds__(256, 2)
void swa_gemm_qkv(const float* __restrict__ A,
                  const float* __restrict__ Wq, const float* __restrict__ bq, float* __restrict__ Cq,
                  const float* __restrict__ Wk, const float* __restrict__ bk, float* __restrict__ Ck,
                  const float* __restrict__ Wv, const float* __restrict__ bv, float* __restrict__ Cv) {
    const float* W; const float* bias; float* C;
    if (blockIdx.z == 0)      { W = Wq; bias = bq; C = Cq; }
    else if (blockIdx.z == 1) { W = Wk; bias = bk; C = Ck; }
    else                      { W = Wv; bias = bv; C = Cv; }
    gemm_body(A, W, bias, C);
}

__global__ __launch_bounds__(256, 2)
void swa_gemm_o(const float* __restrict__ A, const float* __restrict__ W,
                const float* __restrict__ bias, float* __restrict__ C) {
    gemm_body(A, W, bias, C);
}

// ---------------------------------------------------------------------------
// Attention v3: tf32 tensor cores for QK^T and P@V, register-resident online
// softmax in MMA C-fragment layout (quad shuffles). 64 q / block, 128 thr.
// Dynamic smem (floats): Qs[64][68] | Ks[64][68] | Ps[64][68] | Vs[64][72]
// ---------------------------------------------------------------------------
#define AQ_OFF 0
#define AK_OFF 4352
#define AP_OFF 8704
#define AV_OFF 13056
#define ATTN_SMEM_BYTES (17664 * 4)

__global__ __launch_bounds__(128, 3)
void swa_attn3(const float* __restrict__ Q, const float* __restrict__ K,
               const float* __restrict__ V, const float* __restrict__ beta,
               float* __restrict__ O) {
    extern __shared__ float sm[];
    float* Qs = sm + AQ_OFF;
    float* Ks = sm + AK_OFF;
    float* Ps = sm + AP_OFF;
    float* Vs = sm + AV_OFF;

    const int z  = blockIdx.y;
    const int b  = z / H_NUM;
    const int h  = z % H_NUM;
    const int q0 = blockIdx.x * 64;
    const int tid  = threadIdx.x;
    const int lane = tid & 31;
    const int warp = tid >> 5;
    const int g  = lane >> 2;    // quad group 0..7
    const int t4 = lane & 3;     // 0..3

    const float scale = 1.0f / (8.0f * __expf(beta[h]));

    // stage Q (scaled + pre-converted to tf32)
#pragma unroll
    for (int it = 0; it < 8; ++it) {
        const int f = tid + it * 128;
        const int row = f >> 4, c4 = f & 15;
        float4 v = *(const float4*)&Q[((size_t)((q0 + row) * B_SZ + b)) * D_MOD + h * DH_SZ + c4 * 4];
        float4 w;
        w.x = tf32f(v.x * scale); w.y = tf32f(v.y * scale);
        w.z = tf32f(v.z * scale); w.w = tf32f(v.w * scale);
        *(float4*)&Qs[row * 68 + c4 * 4] = w;
    }
    __syncthreads();

    // hold Q A-fragments in registers for the whole kernel
    uint32_t qa[8][4];
    const int r0 = 16 * warp + g;
#pragma unroll
    for (int kk = 0; kk < 8; ++kk) {
        qa[kk][0] = __float_as_uint(Qs[r0 * 68 + kk * 8 + t4]);
        qa[kk][1] = __float_as_uint(Qs[(r0 + 8) * 68 + kk * 8 + t4]);
        qa[kk][2] = __float_as_uint(Qs[r0 * 68 + kk * 8 + t4 + 4]);
        qa[kk][3] = __float_as_uint(Qs[(r0 + 8) * 68 + kk * 8 + t4 + 4]);
    }

    float acc[8][4];
#pragma unroll
    for (int j = 0; j < 8; ++j)
#pragma unroll
        for (int i = 0; i < 4; ++i) acc[j][i] = 0.0f;

    // online softmax state for rows (q0+r0) and (q0+r0+8); sink: m=0, l=1
    float m0 = 0.0f, m1 = 0.0f, l0 = 1.0f, l1 = 1.0f;
    const int qr0 = q0 + r0;
    const int qr1 = qr0 + 8;

    int kbeg = q0 - (WIN_SZ - 1);
    if (kbeg < 0) kbeg = 0;
    kbeg &= ~63;

    for (int t = kbeg; t < q0 + 64; t += 64) {
        // stage K/V tile (tf32-converted)
#pragma unroll
        for (int it = 0; it < 8; ++it) {
            const int f = tid + it * 128;
            const int kk = f >> 4, d4 = f & 15;
            const size_t gofs = ((size_t)((t + kk) * B_SZ + b)) * D_MOD + h * DH_SZ + d4 * 4;
            float4 kv = *(const float4*)&K[gofs];
            float4 vv = *(const float4*)&V[gofs];
            float4 kw, vw;
            kw.x = tf32f(kv.x); kw.y = tf32f(kv.y); kw.z = tf32f(kv.z); kw.w = tf32f(kv.w);
            vw.x = tf32f(vv.x); vw.y = tf32f(vv.y); vw.z = tf32f(vv.z); vw.w = tf32f(vv.w);
            *(float4*)&Ks[kk * 68 + d4 * 4] = kw;
            *(float4*)&Vs[kk * 72 + d4 * 4] = vw;
        }
        __syncthreads();

        // ---- QK^T: S[16 rows][64 keys] per warp ----
        float c[8][4];
#pragma unroll
        for (int j = 0; j < 8; ++j)
#pragma unroll
            for (int i = 0; i < 4; ++i) c[j][i] = 0.0f;

#pragma unroll
        for (int kk = 0; kk < 8; ++kk) {
#pragma unroll
            for (int j = 0; j < 8; ++j) {
                const uint32_t b0 = __float_as_uint(Ks[(j * 8 + g) * 68 + kk * 8 + t4]);
                const uint32_t b1 = __float_as_uint(Ks[(j * 8 + g) * 68 + kk * 8 + t4 + 4]);
                mma_tf32(c[j], qa[kk], b0, b1);
            }
        }

        // ---- mask ----
#pragma unroll
        for (int j = 0; j < 8; ++j) {
            const int k0i = t + j * 8 + 2 * t4;
#pragma unroll
            for (int u = 0; u < 2; ++u) {
                const int kidx = k0i + u;
                const int d0 = qr0 - kidx;
                const int d1 = qr1 - kidx;
                if (!(d0 >= 0 && d0 < WIN_SZ)) c[j][u] = -1e30f;
                if (!(d1 >= 0 && d1 < WIN_SZ)) c[j][2 + u] = -1e30f;
            }
        }

        // ---- online softmax (quad reductions) ----
        float mx0 = m0, mx1 = m1;
#pragma unroll
        for (int j = 0; j < 8; ++j) {
            mx0 = fmaxf(mx0, fmaxf(c[j][0], c[j][1]));
            mx1 = fmaxf(mx1, fmaxf(c[j][2], c[j][3]));
        }
        mx0 = fmaxf(mx0, __shfl_xor_sync(0xffffffffu, mx0, 1));
        mx0 = fmaxf(mx0, __shfl_xor_sync(0xffffffffu, mx0, 2));
        mx1 = fmaxf(mx1, __shfl_xor_sync(0xffffffffu, mx1, 1));
        mx1 = fmaxf(mx1, __shfl_xor_sync(0xffffffffu, mx1, 2));

        const float fs0 = __expf(m0 - mx0);
        const float fs1 = __expf(m1 - mx1);
        float s0 = 0.0f, s1 = 0.0f;
#pragma unroll
        for (int j = 0; j < 8; ++j) {
            const float p0 = __expf(c[j][0] - mx0);
            const float p1 = __expf(c[j][1] - mx0);
            const float p2 = __expf(c[j][2] - mx1);
            const float p3 = __expf(c[j][3] - mx1);
            s0 += p0 + p1;
            s1 += p2 + p3;
            float2 w0, w1;
            w0.x = tf32f(p0); w0.y = tf32f(p1);
            w1.x = tf32f(p2); w1.y = tf32f(p3);
            *(float2*)&Ps[r0 * 68 + j * 8 + 2 * t4] = w0;
            *(float2*)&Ps[(r0 + 8) * 68 + j * 8 + 2 * t4] = w1;
        }
        s0 += __shfl_xor_sync(0xffffffffu, s0, 1);
        s0 += __shfl_xor_sync(0xffffffffu, s0, 2);
        s1 += __shfl_xor_sync(0xffffffffu, s1, 1);
        s1 += __shfl_xor_sync(0xffffffffu, s1, 2);

        l0 = l0 * fs0 + s0;
        l1 = l1 * fs1 + s1;
        m0 = mx0; m1 = mx1;

#pragma unroll
        for (int j = 0; j < 8; ++j) {
            acc[j][0] *= fs0; acc[j][1] *= fs0;
            acc[j][2] *= fs1; acc[j][3] *= fs1;
        }
        __syncwarp();

        // ---- P @ V ----
#pragma unroll
        for (int kk = 0; kk < 8; ++kk) {
            uint32_t pa[4];
            pa[0] = __float_as_uint(Ps[r0 * 68 + kk * 8 + t4]);
            pa[1] = __float_as_uint(Ps[(r0 + 8) * 68 + kk * 8 + t4]);
            pa[2] = __float_as_uint(Ps[r0 * 68 + kk * 8 + t4 + 4]);
            pa[3] = __float_as_uint(Ps[(r0 + 8) * 68 + kk * 8 + t4 + 4]);
#pragma unroll
            for (int j = 0; j < 8; ++j) {
                const uint32_t v0 = __float_as_uint(Vs[(kk * 8 + t4) * 72 + j * 8 + g]);
                const uint32_t v1 = __float_as_uint(Vs[(kk * 8 + t4 + 4) * 72 + j * 8 + g]);
                mma_tf32(acc[j], pa, v0, v1);
            }
        }
        __syncthreads();   // before restaging K/V next tile
    }

    // ---- normalize + store ----
    const float rl0 = 1.0f / l0;
    const float rl1 = 1.0f / l1;
#pragma unroll
    for (int j = 0; j < 8; ++j) {
        const int col = h * DH_SZ + j * 8 + 2 * t4;
        float2 o0, o1;
        o0.x = acc[j][0] * rl0; o0.y = acc[j][1] * rl0;
        o1.x = acc[j][2] * rl1; o1.y = acc[j][3] * rl1;
        *(float2*)&O[((size_t)(qr0 * B_SZ + b)) * D_MOD + col] = o0;
        *(float2*)&O[((size_t)(qr1 * B_SZ + b)) * D_MOD + col] = o1;
    }
}

// ---------------------------------------------------------------------------
extern "C" void kernel_launch(void* const* d_in, const int* in_sizes, int n_in,
                              void* d_out, int out_size) {
    const float* x    = (const float*)d_in[0];
    const float* beta = (const float*)d_in[1];
    const float* Wq   = (const float*)d_in[2];
    const float* bq   = (const float*)d_in[3];
    const float* Wk   = (const float*)d_in[4];
    const float* bk   = (const float*)d_in[5];
    const float* Wv   = (const float*)d_in[6];
    const float* bv   = (const float*)d_in[7];
    const float* Wo   = (const float*)d_in[8];
    const float* bo   = (const float*)d_in[9];
    float* out = (float*)d_out;

    float *Qp, *Kp, *Vp, *Op;
    cudaGetSymbolAddress((void**)&Qp, g_swa_Q);
    cudaGetSymbolAddress((void**)&Kp, g_swa_K);
    cudaGetSymbolAddress((void**)&Vp, g_swa_V);
    cudaGetSymbolAddress((void**)&Op, g_swa_O);

    cudaFuncSetAttribute(swa_attn3, cudaFuncAttributeMaxDynamicSharedMemorySize,
                         ATTN_SMEM_BYTES);

    dim3 qkvgrid(D_MOD / 128, M_ROWS / 128, 3);   // (8, 32, 3)
    swa_gemm_qkv<<<qkvgrid, 256>>>(x, Wq, bq, Qp, Wk, bk, Kp, Wv, bv, Vp);

    dim3 agrid(S_LEN / 64, B_SZ * H_NUM);         // (32, 32)
    swa_attn3<<<agrid, 128, ATTN_SMEM_BYTES>>>(Qp, Kp, Vp, beta, Op);

    dim3 ogrid(D_MOD / 128, M_ROWS / 128);        // (8, 32)
    swa_gemm_o<<<ogrid, 256>>>(Op, Wo, bo, out);
}

// round 5
// speedup vs baseline: 4.0175x; 1.1672x over previous
#include <cuda_runtime.h>
#include <cuda_bf16.h>
#include <cstdint>

#define S_LEN 2048
#define B_SZ  2
#define D_MOD 1024
#define H_NUM 16
#define DH_SZ 64
#define WIN_SZ 256
#define M_ROWS (S_LEN * B_SZ)   // 4096

// Scratch (device globals — no allocation allowed)
__device__ float g_swa_Q[M_ROWS * D_MOD];
__device__ float g_swa_K[M_ROWS * D_MOD];
__device__ float g_swa_V[M_ROWS * D_MOD];
__device__ float g_swa_O[M_ROWS * D_MOD];
__device__ float g_swa_XC[M_ROWS * D_MOD];       // tf32-rounded x
__device__ float g_swa_WT[4 * D_MOD * D_MOD];    // tf32-rounded W^T (q,k,v,o), [n][k]

// ---------------------------------------------------------------------------
__device__ __forceinline__ uint32_t f2tf32(float x) {
    uint32_t r;
    asm("cvt.rna.tf32.f32 %0, %1;" : "=r"(r) : "f"(x));
    return r;
}
__device__ __forceinline__ float tf32f(float x) { return __uint_as_float(f2tf32(x)); }

__device__ __forceinline__ void cp16(uint32_t dst_smem, const void* src) {
    asm volatile("cp.async.cg.shared.global [%0], [%1], 16;"
                 :: "r"(dst_smem), "l"(src));
}

__device__ __forceinline__ void ldsm4(uint32_t& r0, uint32_t& r1, uint32_t& r2,
                                      uint32_t& r3, uint32_t addr) {
    asm volatile("ldmatrix.sync.aligned.m8n8.x4.shared.b16 {%0,%1,%2,%3}, [%4];"
                 : "=r"(r0), "=r"(r1), "=r"(r2), "=r"(r3) : "r"(addr));
}

__device__ __forceinline__ void mma_tf32(float c[4], const uint32_t a[4],
                                         const uint32_t b0, const uint32_t b1) {
    asm volatile(
        "mma.sync.aligned.m16n8k8.row.col.f32.tf32.tf32.f32 "
        "{%0,%1,%2,%3}, {%4,%5,%6,%7}, {%8,%9}, {%0,%1,%2,%3};"
        : "+f"(c[0]), "+f"(c[1]), "+f"(c[2]), "+f"(c[3])
        : "r"(a[0]), "r"(a[1]), "r"(a[2]), "r"(a[3]), "r"(b0), "r"(b1));
}

// ---------------------------------------------------------------------------
// pre-pass: tf32-round x; transpose+round W -> WT[n][k]
// ---------------------------------------------------------------------------
__global__ void swa_prep_x(const float4* __restrict__ x, float4* __restrict__ xc) {
    const int i = blockIdx.x * 256 + threadIdx.x;
    float4 v = x[i];
    v.x = tf32f(v.x); v.y = tf32f(v.y); v.z = tf32f(v.z); v.w = tf32f(v.w);
    xc[i] = v;
}

__global__ void swa_prep_wt(const float* __restrict__ Wq, const float* __restrict__ Wk,
                            const float* __restrict__ Wv, const float* __restrict__ Wo,
                            float* __restrict__ WT) {
    __shared__ float t[32][33];
    const float* W = (blockIdx.z == 0) ? Wq : (blockIdx.z == 1) ? Wk
                   : (blockIdx.z == 2) ? Wv : Wo;
    float* Dst = WT + (size_t)blockIdx.z * D_MOD * D_MOD;
    const int n0 = blockIdx.x * 32, k0 = blockIdx.y * 32;
#pragma unroll
    for (int i = threadIdx.y; i < 32; i += 8)
        t[i][threadIdx.x] = tf32f(W[(size_t)(k0 + i) * D_MOD + n0 + threadIdx.x]);
    __syncthreads();
#pragma unroll
    for (int i = threadIdx.y; i < 32; i += 8)
        Dst[(size_t)(n0 + i) * D_MOD + k0 + threadIdx.x] = t[threadIdx.x][i];
}

// ---------------------------------------------------------------------------
// tf32 mma.sync GEMM with ldmatrix fragments and pre-rounded operands.
// C[4096,1024] = A[m][k] @ WT[n][k]^T + bias.  128x128x32 tiles, 256 threads,
// 8 warps (64x32 warp tiles), cp.async double buffering.
// smem (bytes): As0@0  As1@18432  Bs0@36864  Bs1@55296   (pitch 36 floats)
// ---------------------------------------------------------------------------
#define GPITCH 36
#define GEMM_SMEM 73728

__device__ __forceinline__
void gemm_body(const float* __restrict__ A, const float* __restrict__ B,
               const float* __restrict__ bias, float* __restrict__ C) {
    extern __shared__ float sm[];
    const uint32_t smb = (uint32_t)__cvta_generic_to_shared(sm);
    const int tid  = threadIdx.x;
    const int lane = tid & 31;
    const int warp = tid >> 5;
    const int wr   = warp & 1;
    const int wc   = warp >> 1;
    const int m0   = blockIdx.y * 128;
    const int n0   = blockIdx.x * 128;

    const float* Ab = A + (size_t)m0 * 1024;
    const float* Bb = B + (size_t)n0 * 1024;

    // cp.async mapping: 4 float4 per thread per operand per 32-k chunk
    const int sr = tid >> 3;          // 0..31 base row
    const int sf = tid & 7;           // float4 col 0..7
    // ldmatrix per-lane offsets (bytes), pitch = 144 B
    const int mi = lane >> 3, rr = lane & 7;
    uint32_t aOff[4], bOff[2];
#pragma unroll
    for (int mt = 0; mt < 4; ++mt) {
        const int row = wr * 64 + mt * 16 + (mi & 1) * 8 + rr;
        aOff[mt] = (uint32_t)(row * GPITCH + (mi >> 1) * 4) * 4;
    }
#pragma unroll
    for (int p = 0; p < 2; ++p) {
        const int row = wc * 32 + p * 16 + (mi >> 1) * 8 + rr;
        bOff[p] = (uint32_t)(row * GPITCH + (mi & 1) * 4) * 4;
    }

    float acc[4][4][4];
#pragma unroll
    for (int mt = 0; mt < 4; ++mt)
#pragma unroll
        for (int nt = 0; nt < 4; ++nt)
#pragma unroll
            for (int i = 0; i < 4; ++i) acc[mt][nt][i] = 0.0f;

    auto stage = [&](int kc) {
        const uint32_t as = smb + ((kc & 1) ? 18432u : 0u);
        const uint32_t bs = smb + ((kc & 1) ? 55296u : 36864u);
        const int k0 = kc * 32;
#pragma unroll
        for (int i = 0; i < 4; ++i) {
            const int r = sr + i * 32;
            cp16(as + (uint32_t)(r * 144 + sf * 16), Ab + (size_t)r * 1024 + k0 + sf * 4);
            cp16(bs + (uint32_t)(r * 144 + sf * 16), Bb + (size_t)r * 1024 + k0 + sf * 4);
        }
    };

    stage(0);
    asm volatile("cp.async.commit_group;");

    const int NIT = 1024 / 32;
    for (int kc = 0; kc < NIT; ++kc) {
        if (kc + 1 < NIT) {
            stage(kc + 1);
            asm volatile("cp.async.commit_group;");
            asm volatile("cp.async.wait_group 1;");
        } else {
            asm volatile("cp.async.wait_group 0;");
        }
        __syncthreads();

        const uint32_t as = smb + ((kc & 1) ? 18432u : 0u);
        const uint32_t bs = smb + ((kc & 1) ? 55296u : 36864u);
#pragma unroll
        for (int ks = 0; ks < 4; ++ks) {
            const uint32_t kb = (uint32_t)(ks * 8 * 4);
            uint32_t af[4][4], bf[2][4];
#pragma unroll
            for (int mt = 0; mt < 4; ++mt)
                ldsm4(af[mt][0], af[mt][1], af[mt][2], af[mt][3], as + aOff[mt] + kb);
#pragma unroll
            for (int p = 0; p < 2; ++p)
                ldsm4(bf[p][0], bf[p][1], bf[p][2], bf[p][3], bs + bOff[p] + kb);
#pragma unroll
            for (int mt = 0; mt < 4; ++mt)
#pragma unroll
                for (int p = 0; p < 2; ++p) {
                    mma_tf32(acc[mt][2 * p + 0], af[mt], bf[p][0], bf[p][1]);
                    mma_tf32(acc[mt][2 * p + 1], af[mt], bf[p][2], bf[p][3]);
                }
        }
        __syncthreads();
    }

    // epilogue
#pragma unroll
    for (int mt = 0; mt < 4; ++mt) {
        const int row = m0 + wr * 64 + mt * 16 + (lane >> 2);
#pragma unroll
        for (int nt = 0; nt < 4; ++nt) {
            const int col = n0 + wc * 32 + nt * 8 + 2 * (lane & 3);
            const float2 bia = *(const float2*)&bias[col];
            float2 o0, o1;
            o0.x = acc[mt][nt][0] + bia.x;
            o0.y = acc[mt][nt][1] + bia.y;
            o1.x = acc[mt][nt][2] + bia.x;
            o1.y = acc[mt][nt][3] + bia.y;
            *(float2*)&C[(size_t)row * 1024 + col] = o0;
            *(float2*)&C[(size_t)(row + 8) * 1024 + col] = o1;
        }
    }
}

__global__ __launch_bounds__(256, 2)
void swa_gemm_qkv(const float* __restrict__ xc, const float* __restrict__ WT,
                  const float* __restrict__ bq, const float* __restrict__ bk,
                  const float* __restrict__ bv,
                  float* __restrict__ Q, float* __restrict__ K, float* __restrict__ V) {
    const int z = blockIdx.z;
    const float* W = WT + (size_t)z * D_MOD * D_MOD;
    const float* bias = (z == 0) ? bq : (z == 1) ? bk : bv;
    float* C = (z == 0) ? Q : (z == 1) ? K : V;
    gemm_body(xc, W, bias, C);
}

__global__ __launch_bounds__(256, 2)
void swa_gemm_o(const float* __restrict__ A, const float* __restrict__ WT,
                const float* __restrict__ bias, float* __restrict__ C) {
    gemm_body(A, WT + (size_t)3 * D_MOD * D_MOD, bias, C);
}

// ---------------------------------------------------------------------------
// Attention (R3, proven): tf32 mma QK^T and P@V, register online softmax.
// ---------------------------------------------------------------------------
#define AQ_OFF 0
#define AK_OFF 4352
#define AP_OFF 8704
#define AV_OFF 13056
#define ATTN_SMEM_BYTES (17664 * 4)

__global__ __launch_bounds__(128, 3)
void swa_attn3(const float* __restrict__ Q, const float* __restrict__ K,
               const float* __restrict__ V, const float* __restrict__ beta,
               float* __restrict__ O) {
    extern __shared__ float smf[];
    float* Qs = smf + AQ_OFF;
    float* Ks = smf + AK_OFF;
    float* Ps = smf + AP_OFF;
    float* Vs = smf + AV_OFF;

    const int z  = blockIdx.y;
    const int b  = z / H_NUM;
    const int h  = z % H_NUM;
    const int q0 = blockIdx.x * 64;
    const int tid  = threadIdx.x;
    const int lane = tid & 31;
    const int warp = tid >> 5;
    const int g  = lane >> 2;
    const int t4 = lane & 3;

    const float scale = 1.0f / (8.0f * __expf(beta[h]));

#pragma unroll
    for (int it = 0; it < 8; ++it) {
        const int f = tid + it * 128;
        const int row = f >> 4, c4 = f & 15;
        float4 v = *(const float4*)&Q[((size_t)((q0 + row) * B_SZ + b)) * D_MOD + h * DH_SZ + c4 * 4];
        float4 w;
        w.x = tf32f(v.x * scale); w.y = tf32f(v.y * scale);
        w.z = tf32f(v.z * scale); w.w = tf32f(v.w * scale);
        *(float4*)&Qs[row * 68 + c4 * 4] = w;
    }
    __syncthreads();

    uint32_t qa[8][4];
    const int r0 = 16 * warp + g;
#pragma unroll
    for (int kk = 0; kk < 8; ++kk) {
        qa[kk][0] = __float_as_uint(Qs[r0 * 68 + kk * 8 + t4]);
        qa[kk][1] = __float_as_uint(Qs[(r0 + 8) * 68 + kk * 8 + t4]);
        qa[kk][2] = __float_as_uint(Qs[r0 * 68 + kk * 8 + t4 + 4]);
        qa[kk][3] = __float_as_uint(Qs[(r0 + 8) * 68 + kk * 8 + t4 + 4]);
    }

    float acc[8][4];
#pragma unroll
    for (int j = 0; j < 8; ++j)
#pragma unroll
        for (int i = 0; i < 4; ++i) acc[j][i] = 0.0f;

    float m0 = 0.0f, m1 = 0.0f, l0 = 1.0f, l1 = 1.0f;
    const int qr0 = q0 + r0;
    const int qr1 = qr0 + 8;

    int kbeg = q0 - (WIN_SZ - 1);
    if (kbeg < 0) kbeg = 0;
    kbeg &= ~63;

    for (int t = kbeg; t < q0 + 64; t += 64) {
#pragma unroll
        for (int it = 0; it < 8; ++it) {
            const int f = tid + it * 128;
            const int kk = f >> 4, d4 = f & 15;
            const size_t gofs = ((size_t)((t + kk) * B_SZ + b)) * D_MOD + h * DH_SZ + d4 * 4;
            float4 kv = *(const float4*)&K[gofs];
            float4 vv = *(const float4*)&V[gofs];
            float4 kw, vw;
            kw.x = tf32f(kv.x); kw.y = tf32f(kv.y); kw.z = tf32f(kv.z); kw.w = tf32f(kv.w);
            vw.x = tf32f(vv.x); vw.y = tf32f(vv.y); vw.z = tf32f(vv.z); vw.w = tf32f(vv.w);
            *(float4*)&Ks[kk * 68 + d4 * 4] = kw;
            *(float4*)&Vs[kk * 72 + d4 * 4] = vw;
        }
        __syncthreads();

        float c[8][4];
#pragma unroll
        for (int j = 0; j < 8; ++j)
#pragma unroll
            for (int i = 0; i < 4; ++i) c[j][i] = 0.0f;

#pragma unroll
        for (int kk = 0; kk < 8; ++kk) {
#pragma unroll
            for (int j = 0; j < 8; ++j) {
                const uint32_t b0 = __float_as_uint(Ks[(j * 8 + g) * 68 + kk * 8 + t4]);
                const uint32_t b1 = __float_as_uint(Ks[(j * 8 + g) * 68 + kk * 8 + t4 + 4]);
                mma_tf32(c[j], qa[kk], b0, b1);
            }
        }

#pragma unroll
        for (int j = 0; j < 8; ++j) {
            const int k0i = t + j * 8 + 2 * t4;
#pragma unroll
            for (int u = 0; u < 2; ++u) {
                const int kidx = k0i + u;
                const int d0 = qr0 - kidx;
                const int d1 = qr1 - kidx;
                if (!(d0 >= 0 && d0 < WIN_SZ)) c[j][u] = -1e30f;
                if (!(d1 >= 0 && d1 < WIN_SZ)) c[j][2 + u] = -1e30f;
            }
        }

        float mx0 = m0, mx1 = m1;
#pragma unroll
        for (int j = 0; j < 8; ++j) {
            mx0 = fmaxf(mx0, fmaxf(c[j][0], c[j][1]));
            mx1 = fmaxf(mx1, fmaxf(c[j][2], c[j][3]));
        }
        mx0 = fmaxf(mx0, __shfl_xor_sync(0xffffffffu, mx0, 1));
        mx0 = fmaxf(mx0, __shfl_xor_sync(0xffffffffu, mx0, 2));
        mx1 = fmaxf(mx1, __shfl_xor_sync(0xffffffffu, mx1, 1));
        mx1 = fmaxf(mx1, __shfl_xor_sync(0xffffffffu, mx1, 2));

        const float fs0 = __expf(m0 - mx0);
        const float fs1 = __expf(m1 - mx1);
        float s0 = 0.0f, s1 = 0.0f;
#pragma unroll
        for (int j = 0; j < 8; ++j) {
            const float p0 = __expf(c[j][0] - mx0);
            const float p1 = __expf(c[j][1] - mx0);
            const float p2 = __expf(c[j][2] - mx1);
            const float p3 = __expf(c[j][3] - mx1);
            s0 += p0 + p1;
            s1 += p2 + p3;
            float2 w0, w1;
            w0.x = tf32f(p0); w0.y = tf32f(p1);
            w1.x = tf32f(p2); w1.y = tf32f(p3);
            *(float2*)&Ps[r0 * 68 + j * 8 + 2 * t4] = w0;
            *(float2*)&Ps[(r0 + 8) * 68 + j * 8 + 2 * t4] = w1;
        }
        s0 += __shfl_xor_sync(0xffffffffu, s0, 1);
        s0 += __shfl_xor_sync(0xffffffffu, s0, 2);
        s1 += __shfl_xor_sync(0xffffffffu, s1, 1);
        s1 += __shfl_xor_sync(0xffffffffu, s1, 2);

        l0 = l0 * fs0 + s0;
        l1 = l1 * fs1 + s1;
        m0 = mx0; m1 = mx1;

#pragma unroll
        for (int j = 0; j < 8; ++j) {
            acc[j][0] *= fs0; acc[j][1] *= fs0;
            acc[j][2] *= fs1; acc[j][3] *= fs1;
        }
        __syncwarp();

#pragma unroll
        for (int kk = 0; kk < 8; ++kk) {
            uint32_t pa[4];
            pa[0] = __float_as_uint(Ps[r0 * 68 + kk * 8 + t4]);
            pa[1] = __float_as_uint(Ps[(r0 + 8) * 68 + kk * 8 + t4]);
            pa[2] = __float_as_uint(Ps[r0 * 68 + kk * 8 + t4 + 4]);
            pa[3] = __float_as_uint(Ps[(r0 + 8) * 68 + kk * 8 + t4 + 4]);
#pragma unroll
            for (int j = 0; j < 8; ++j) {
                const uint32_t v0 = __float_as_uint(Vs[(kk * 8 + t4) * 72 + j * 8 + g]);
                const uint32_t v1 = __float_as_uint(Vs[(kk * 8 + t4 + 4) * 72 + j * 8 + g]);
                mma_tf32(acc[j], pa, v0, v1);
            }
        }
        __syncthreads();
    }

    // normalize + store (tf32-rounded so the O-GEMM stages raw)
    const float rl0 = 1.0f / l0;
    const float rl1 = 1.0f / l1;
#pragma unroll
    for (int j = 0; j < 8; ++j) {
        const int col = h * DH_SZ + j * 8 + 2 * t4;
        float2 o0, o1;
        o0.x = tf32f(acc[j][0] * rl0); o0.y = tf32f(acc[j][1] * rl0);
        o1.x = tf32f(acc[j][2] * rl1); o1.y = tf32f(acc[j][3] * rl1);
        *(float2*)&O[((size_t)(qr0 * B_SZ + b)) * D_MOD + col] = o0;
        *(float2*)&O[((size_t)(qr1 * B_SZ + b)) * D_MOD + col] = o1;
    }
}

// ---------------------------------------------------------------------------
extern "C" void kernel_launch(void* const* d_in, const int* in_sizes, int n_in,
                              void* d_out, int out_size) {
    const float* x    = (const float*)d_in[0];
    const float* beta = (const float*)d_in[1];
    const float* Wq   = (const float*)d_in[2];
    const float* bq   = (const float*)d_in[3];
    const float* Wk   = (const float*)d_in[4];
    const float* bk   = (const float*)d_in[5];
    const float* Wv   = (const float*)d_in[6];
    const float* bv   = (const float*)d_in[7];
    const float* Wo   = (const float*)d_in[8];
    const float* bo   = (const float*)d_in[9];
    float* out = (float*)d_out;

    float *Qp, *Kp, *Vp, *Op, *XCp, *WTp;
    cudaGetSymbolAddress((void**)&Qp,  g_swa_Q);
    cudaGetSymbolAddress((void**)&Kp,  g_swa_K);
    cudaGetSymbolAddress((void**)&Vp,  g_swa_V);
    cudaGetSymbolAddress((void**)&Op,  g_swa_O);
    cudaGetSymbolAddress((void**)&XCp, g_swa_XC);
    cudaGetSymbolAddress((void**)&WTp, g_swa_WT);

    cudaFuncSetAttribute(swa_attn3, cudaFuncAttributeMaxDynamicSharedMemorySize,
                         ATTN_SMEM_BYTES);
    cudaFuncSetAttribute(swa_gemm_qkv, cudaFuncAttributeMaxDynamicSharedMemorySize,
                         GEMM_SMEM);
    cudaFuncSetAttribute(swa_gemm_o, cudaFuncAttributeMaxDynamicSharedMemorySize,
                         GEMM_SMEM);

    swa_prep_x<<<(M_ROWS * D_MOD / 4) / 256, 256>>>((const float4*)x, (float4*)XCp);
    swa_prep_wt<<<dim3(32, 32, 4), dim3(32, 8)>>>(Wq, Wk, Wv, Wo, WTp);

    dim3 qkvgrid(D_MOD / 128, M_ROWS / 128, 3);   // (8, 32, 3)
    swa_gemm_qkv<<<qkvgrid, 256, GEMM_SMEM>>>(XCp, WTp, bq, bk, bv, Qp, Kp, Vp);

    dim3 agrid(S_LEN / 64, B_SZ * H_NUM);         // (32, 32)
    swa_attn3<<<agrid, 128, ATTN_SMEM_BYTES>>>(Qp, Kp, Vp, beta, Op);

    dim3 ogrid(D_MOD / 128, M_ROWS / 128);        // (8, 32)
    swa_gemm_o<<<ogrid, 256, GEMM_SMEM>>>(Op, WTp, bo, out);
}